// round 14
// baseline (speedup 1.0000x reference)
#include <cuda_runtime.h>
#include <cuda_bf16.h>
#include <math.h>
#include <stdint.h>

// ---------------------------------------------------------------------------
// Problem constants
// ---------------------------------------------------------------------------
#define NN   32768
#define IN_C 256
#define DD   128
#define HH   4
#define HD   512
#define MM   4
#define KPP  128
#define SSZ  256
#define RR   (KPP*MM)
#define INV_SCALE 0.088388347648318447f   // 1/sqrt(128)

// ---------------------------------------------------------------------------
// Scratch (static device globals; no allocation allowed)
// ---------------------------------------------------------------------------
__device__ float    g_xself[(size_t)NN*DD];      // exact fp32 x_self
__device__ uint32_t g_outLb[(size_t)NN*256];     // packed bf16x2 attention outs
__device__ uint32_t g_outGb[(size_t)NN*256];
__device__ uint32_t g_Qb[(size_t)NN*256];        // packed bf16x2, pre-scaled
__device__ uint32_t g_Kb[(size_t)NN*256];
__device__ uint32_t g_Vb[(size_t)NN*256];
__device__ uint32_t g_repKb[(size_t)RR*256];     // [rep][h*64+dp]
__device__ uint32_t g_repVb2[(size_t)(RR/2)*512];// [rpair][h*128+d] cross-packed
// GEMM operands
__device__ uint32_t g_xh_t[(size_t)128*NN];      // [kp][m] hi (transposed)
__device__ uint32_t g_xl_t[(size_t)128*NN];      // [kp][m] lo
__device__ uint32_t g_Wh[3][(IN_C/2)*HD];        // [kp][n] hi
__device__ uint32_t g_Wah[128*128];              // Wv head-avg hi  [kp][d]
__device__ uint32_t g_Wal[128*128];              // Wv head-avg lo

// ---------------------------------------------------------------------------
// helpers
// ---------------------------------------------------------------------------
__device__ __forceinline__ float bfr(float v) {
    return __bfloat162float(__float2bfloat16(v));
}
__device__ __forceinline__ uint32_t bf2(float lo, float hi) {
    uint32_t r;
    asm("cvt.rn.bf16x2.f32 %0, %1, %2;" : "=r"(r) : "f"(hi), "f"(lo));
    return r;
}
__device__ __forceinline__ float bflo(uint32_t u) { return __uint_as_float(u << 16); }
__device__ __forceinline__ float bfhi(uint32_t u) { return __uint_as_float(u & 0xffff0000u); }
__device__ __forceinline__ uint32_t prmt(uint32_t a, uint32_t b, uint32_t sel) {
    uint32_t r;
    asm("prmt.b32 %0, %1, %2, %3;" : "=r"(r) : "r"(a), "r"(b), "r"(sel));
    return r;
}
__device__ __forceinline__ void mma_bf16(float4& d, const uint32_t a[4],
                                         uint32_t b0, uint32_t b1) {
    asm volatile(
        "mma.sync.aligned.m16n8k16.row.col.f32.bf16.bf16.f32 "
        "{%0,%1,%2,%3}, {%4,%5,%6,%7}, {%8,%9}, {%0,%1,%2,%3};"
        : "+f"(d.x), "+f"(d.y), "+f"(d.z), "+f"(d.w)
        : "r"(a[0]), "r"(a[1]), "r"(a[2]), "r"(a[3]), "r"(b0), "r"(b1));
}
#define CP_ASYNC16(dst, src) \
    asm volatile("cp.async.cg.shared.global [%0], [%1], 16;" :: "r"(dst), "l"(src))
#define CP_COMMIT() asm volatile("cp.async.commit_group;")
#define CP_WAIT(n)  asm volatile("cp.async.wait_group %0;" :: "n"(n))

__device__ __forceinline__ uint32_t smem_u32addr(const void* p) {
    uint32_t a;
    asm("{ .reg .u64 t; cvta.to.shared.u64 t, %1; cvt.u32.u64 %0, t; }"
        : "=r"(a) : "l"(p));
    return a;
}

__device__ __forceinline__ float warp_max2(float s) {
    s = fmaxf(s, __shfl_xor_sync(0xffffffffu, s, 1));
    s = fmaxf(s, __shfl_xor_sync(0xffffffffu, s, 2));
    return s;
}
__device__ __forceinline__ float warp_sum2(float s) {
    s += __shfl_xor_sync(0xffffffffu, s, 1);
    s += __shfl_xor_sync(0xffffffffu, s, 2);
    return s;
}
__device__ __forceinline__ float warp_max32(float s) {
#pragma unroll
    for (int o = 16; o > 0; o >>= 1) s = fmaxf(s, __shfl_xor_sync(0xffffffffu, s, o));
    return s;
}
__device__ __forceinline__ float warp_sum32(float s) {
#pragma unroll
    for (int o = 16; o > 0; o >>= 1) s += __shfl_xor_sync(0xffffffffu, s, o);
    return s;
}

// ---------------------------------------------------------------------------
// split_xt: x -> transposed hi/lo bf16x2 splits  g_x{h,l}_t [kp][m]
// ---------------------------------------------------------------------------
__global__ __launch_bounds__(256) void split_xt(const float* __restrict__ x)
{
    __shared__ uint32_t Th[32][132];
    __shared__ uint32_t Tl[32][132];
    const int m0 = blockIdx.x * 128;
    const int tid = threadIdx.x;
#pragma unroll
    for (int c = 0; c < 4; c++) {
        const int kpb = c * 32;
        {
            const int m = tid >> 1, half = tid & 1;
            const float* src = x + (size_t)(m0 + m) * IN_C + (kpb + half * 16) * 2;
#pragma unroll
            for (int j = 0; j < 16; j++) {
                float2 v = *(const float2*)(src + 2 * j);
                const float h0 = bfr(v.x), h1 = bfr(v.y);
                Th[half * 16 + j][m] = bf2(v.x, v.y);
                Tl[half * 16 + j][m] = bf2(v.x - h0, v.y - h1);
            }
        }
        __syncthreads();
        {
            const int kpr = tid >> 3, mo = (tid & 7) * 16;
            uint32_t* dh = g_xh_t + (size_t)(kpb + kpr) * NN + m0 + mo;
            uint32_t* dl = g_xl_t + (size_t)(kpb + kpr) * NN + m0 + mo;
#pragma unroll
            for (int j = 0; j < 4; j++) {
                *(uint4*)(dh + 4 * j) = *(uint4*)&Th[kpr][mo + 4 * j];
                *(uint4*)(dl + 4 * j) = *(uint4*)&Tl[kpr][mo + 4 * j];
            }
        }
        __syncthreads();
    }
}

// ---------------------------------------------------------------------------
// split_w: W -> hi bf16x2  g_Wh [kp][n]
// ---------------------------------------------------------------------------
__global__ __launch_bounds__(256) void split_w(
    const float* __restrict__ Wq, const float* __restrict__ Wk,
    const float* __restrict__ Wv)
{
    const float* W = (blockIdx.y == 0) ? Wq : (blockIdx.y == 1) ? Wk : Wv;
    const int idx = blockIdx.x * 256 + threadIdx.x;
    const int kp = idx >> 9, n = idx & 511;
    const float v0 = W[(size_t)(2 * kp) * HD + n];
    const float v1 = W[(size_t)(2 * kp + 1) * HD + n];
    g_Wh[blockIdx.y][idx] = bf2(v0, v1);
}

// ---------------------------------------------------------------------------
// wavg_split: Wavg[k][d] = mean_h Wv[k][h*128+d], hi/lo split
// ---------------------------------------------------------------------------
__global__ __launch_bounds__(256) void wavg_split(const float* __restrict__ Wv)
{
    const int idx = blockIdx.x * 256 + threadIdx.x;
    const int kp = idx >> 7, d = idx & 127;
    const float* r0 = Wv + (size_t)(2 * kp) * HD;
    const float* r1 = Wv + (size_t)(2 * kp + 1) * HD;
    const float v0 = 0.25f * (r0[d] + r0[128 + d] + r0[256 + d] + r0[384 + d]);
    const float v1 = 0.25f * (r1[d] + r1[128 + d] + r1[256 + d] + r1[384 + d]);
    const float h0 = bfr(v0), h1 = bfr(v1);
    g_Wah[idx] = bf2(v0, v1);
    g_Wal[idx] = bf2(v0 - h0, v1 - h1);
}

// ---------------------------------------------------------------------------
// Kernel 1: unified A-resident QKV GEMM, 64-row slabs -> 3 blocks/SM.
// Block = one 64-row slab x one 128-col slab; full-K A resident (36 KB);
// z in {Q,K,V} looped; B streamed via 4-deep cp.async ring (34 KB).
// Warps: 2M x 4N, warp tile 32m x 32n.
// ---------------------------------------------------------------------------
#define GSTG 2176                        // 16*136 u32 per B stage
#define ASMEM (128 * 72)                 // full-K A tile, 64 m cols + pad
#define GEMM_SMEM_BYTES ((ASMEM + 4 * GSTG) * 4)

__global__ __launch_bounds__(256) void qkv_gemm_tc(
    const float* __restrict__ bq, const float* __restrict__ bk,
    const float* __restrict__ bv)
{
    extern __shared__ uint32_t smg[];
    uint32_t* Asm = smg;                 // [128 kp][72 m]
    uint32_t* Bbuf = smg + ASMEM;        // 4 x [16 kp][136 n]

    const int tid  = threadIdx.x;
    const int warp = tid >> 5, lane = tid & 31;
    const int lr = lane >> 2, lc = lane & 3;
    const int wm = warp & 1, wn = warp >> 1;    // 2M x 4N warp grid
    const int row0 = blockIdx.y * 64;
    const int col0 = blockIdx.x * 128;

    // ---- load full-K A tile (one cp.async group) ----
    {
        const uint32_t abase = smem_u32addr(Asm);
#pragma unroll
        for (int j = 0; j < 8; j++) {
            const int cid = j * 256 + tid;          // 2048 16B chunks
            const int kpr = cid >> 4, f = (cid & 15) * 4;
            CP_ASYNC16(abase + (kpr * 72 + f) * 4,
                       g_xh_t + (size_t)kpr * NN + row0 + f);
        }
        CP_COMMIT();
    }

    auto issueB = [&](int st) {
        const int z = st >> 3, kp0 = (st & 7) * 16;
        const uint32_t base = smem_u32addr(Bbuf + (st & 3) * GSTG);
        const uint32_t* WH = g_Wh[z];
#pragma unroll
        for (int j = 0; j < 2; j++) {
            const int slot = tid * 2 + j;
            const int kpr = slot >> 5, f = (slot & 31) * 4;
            CP_ASYNC16(base + (kpr * 136 + f) * 4,
                       WH + (size_t)(kp0 + kpr) * HD + col0 + f);
        }
        CP_COMMIT();
    };

    issueB(0); issueB(1); issueB(2); issueB(3);

    float4 acc[2][4];                    // 32m x 32n warp tile
#pragma unroll
    for (int mi = 0; mi < 2; mi++)
#pragma unroll
        for (int ni = 0; ni < 4; ni++)
            acc[mi][ni] = make_float4(0.f, 0.f, 0.f, 0.f);

#pragma unroll 1
    for (int st = 0; st < 24; st++) {
        if (st < 21)      CP_WAIT(3);
        else if (st == 21) CP_WAIT(2);
        else if (st == 22) CP_WAIT(1);
        else               CP_WAIT(0);
        __syncthreads();

        const uint32_t* Bh = Bbuf + (st & 3) * GSTG;
        const int ks = (st & 7) * 16;

#pragma unroll
        for (int kf = 0; kf < 2; kf++) {
            const int ra0 = (ks + kf * 8 + lc) * 72;
            const int ra1 = (ks + kf * 8 + lc + 4) * 72;
            const int rb0 = (kf * 8 + lc) * 136;
            const int rb1 = (kf * 8 + lc + 4) * 136;
            uint32_t ah[2][4];
#pragma unroll
            for (int mi = 0; mi < 2; mi++) {
                const int m0 = wm * 32 + mi * 16 + lr;
                ah[mi][0] = Asm[ra0 + m0]; ah[mi][1] = Asm[ra0 + m0 + 8];
                ah[mi][2] = Asm[ra1 + m0]; ah[mi][3] = Asm[ra1 + m0 + 8];
            }
#pragma unroll
            for (int ni = 0; ni < 4; ni++) {
                const int n0 = wn * 32 + ni * 8 + lr;
                const uint32_t bh0 = Bh[rb0 + n0], bh1 = Bh[rb1 + n0];
#pragma unroll
                for (int mi = 0; mi < 2; mi++)
                    mma_bf16(acc[mi][ni], ah[mi], bh0, bh1);
            }
        }

        // ---- epilogue at end of each matrix ----
        if ((st & 7) == 7) {
            const int z = st >> 3;
            const float* bias = (z == 0) ? bq : (z == 1) ? bk : bv;
            uint32_t* Cb = (z == 0) ? g_Qb : (z == 1) ? g_Kb : g_Vb;
#pragma unroll
            for (int mi = 0; mi < 2; mi++) {
                const int r = row0 + wm * 32 + mi * 16 + lr;
#pragma unroll
                for (int ni = 0; ni < 4; ni++) {
                    const int c = col0 + wn * 32 + ni * 8 + 2 * lc;
                    const float2 b2 = *(const float2*)&bias[c];
                    float x0 = acc[mi][ni].x + b2.x, y0 = acc[mi][ni].y + b2.y;
                    float x1 = acc[mi][ni].z + b2.x, y1 = acc[mi][ni].w + b2.y;
                    if (z == 0) { x0 *= INV_SCALE; y0 *= INV_SCALE;
                                  x1 *= INV_SCALE; y1 *= INV_SCALE; }
                    const int cp = c >> 1;
                    Cb[(size_t)r * 256 + cp]       = bf2(x0, y0);
                    Cb[(size_t)(r + 8) * 256 + cp] = bf2(x1, y1);
                    acc[mi][ni] = make_float4(0.f, 0.f, 0.f, 0.f);
                }
            }
        }

        __syncthreads();
        if (st + 4 < 24) issueB(st + 4);
    }
}

// ---------------------------------------------------------------------------
// Kernel 1b: exact x_self GEMM (M=NN, K=256, N=128), 3-term bf16 split,
// 64x32 warp tiles (2M x 4N).
// ---------------------------------------------------------------------------
__global__ __launch_bounds__(256) void xself_gemm(const float* __restrict__ bv)
{
    extern __shared__ uint32_t smx[];

    const int tid  = threadIdx.x;
    const int warp = tid >> 5, lane = tid & 31;
    const int lr = lane >> 2, lc = lane & 3;
    const int wm = warp & 1, wn = warp >> 1;    // 2M x 4N
    const int row0 = blockIdx.x * 128;

    auto issue = [&](int it, int b) {
        const int kp0 = it * 16;
        const uint32_t base = smem_u32addr(smx + b * 4 * GSTG);
#pragma unroll
        for (int j = 0; j < 2; j++) {
            const int slot = tid * 2 + j;
            const int kpr = slot >> 5, f = (slot & 31) * 4;
            const uint32_t doff = (kpr * 136 + f) * 4;
            const size_t asrc = (size_t)(kp0 + kpr) * NN + row0 + f;
            const size_t bsrc = (size_t)(kp0 + kpr) * 128 + f;
            CP_ASYNC16(base + 0 * GSTG * 4 + doff, g_xh_t + asrc);
            CP_ASYNC16(base + 1 * GSTG * 4 + doff, g_xl_t + asrc);
            CP_ASYNC16(base + 2 * GSTG * 4 + doff, g_Wah + bsrc);
            CP_ASYNC16(base + 3 * GSTG * 4 + doff, g_Wal + bsrc);
        }
    };

    float4 acc[4][4];
#pragma unroll
    for (int mi = 0; mi < 4; mi++)
#pragma unroll
        for (int ni = 0; ni < 4; ni++)
            acc[mi][ni] = make_float4(0.f, 0.f, 0.f, 0.f);

    issue(0, 0); CP_COMMIT();

    for (int it = 0; it < 8; it++) {
        if (it < 7) { issue(it + 1, (it + 1) & 1); CP_COMMIT(); CP_WAIT(1); }
        else        { CP_WAIT(0); }
        __syncthreads();

        const uint32_t* buf = smx + (it & 1) * 4 * GSTG;
        const uint32_t* Ah = buf;
        const uint32_t* Al = buf + GSTG;
        const uint32_t* Bh = buf + 2 * GSTG;
        const uint32_t* Bl = buf + 3 * GSTG;

#pragma unroll
        for (int kf = 0; kf < 2; kf++) {
            const int r0 = (kf * 8 + lc) * 136;
            const int r1 = (kf * 8 + lc + 4) * 136;
            uint32_t ah[4][4], al[4][4];
#pragma unroll
            for (int mi = 0; mi < 4; mi++) {
                const int m0 = wm * 64 + mi * 16 + lr;
                ah[mi][0] = Ah[r0 + m0]; ah[mi][1] = Ah[r0 + m0 + 8];
                ah[mi][2] = Ah[r1 + m0]; ah[mi][3] = Ah[r1 + m0 + 8];
                al[mi][0] = Al[r0 + m0]; al[mi][1] = Al[r0 + m0 + 8];
                al[mi][2] = Al[r1 + m0]; al[mi][3] = Al[r1 + m0 + 8];
            }
#pragma unroll
            for (int ni = 0; ni < 4; ni++) {
                const int n0 = wn * 32 + ni * 8 + lr;
                const uint32_t bh0 = Bh[r0 + n0], bh1 = Bh[r1 + n0];
                const uint32_t bl0 = Bl[r0 + n0], bl1 = Bl[r1 + n0];
#pragma unroll
                for (int mi = 0; mi < 4; mi++) {
                    mma_bf16(acc[mi][ni], ah[mi], bh0, bh1);
                    mma_bf16(acc[mi][ni], ah[mi], bl0, bl1);
                    mma_bf16(acc[mi][ni], al[mi], bh0, bh1);
                }
            }
        }
        __syncthreads();
    }

#pragma unroll
    for (int mi = 0; mi < 4; mi++) {
        const int r = row0 + wm * 64 + mi * 16 + lr;
#pragma unroll
        for (int ni = 0; ni < 4; ni++) {
            const int c = wn * 32 + ni * 8 + 2 * lc;
            const float bx = 0.25f * (bv[c] + bv[128 + c] + bv[256 + c] + bv[384 + c]);
            const float by = 0.25f * (bv[c+1] + bv[129 + c] + bv[257 + c] + bv[385 + c]);
            *(float2*)&g_xself[(size_t)r * DD + c] =
                make_float2(acc[mi][ni].x + bx, acc[mi][ni].y + by);
            *(float2*)&g_xself[(size_t)(r + 8) * DD + c] =
                make_float2(acc[mi][ni].z + bx, acc[mi][ni].w + by);
        }
    }
}

// ---------------------------------------------------------------------------
// Kernel 2: fine attention (z-split) + ONLINE coarse pooling.
// K/V streamed in two 128-key halves -> smem ~72 KB -> 3 blocks/SM.
//   Kr [128 key][68], Vr [64 kpair][136]
//   scratch: qsm u32[2][64] | ps f[2][128] | rka f[2][128] | rva f[2][128] | mls f[8]
// ---------------------------------------------------------------------------
#define FINE_SCR (128 + 256 + 256 + 256 + 8)
#define FINE_SMEM_BYTES ((128*68 + 64*136 + FINE_SCR) * 4)

__global__ __launch_bounds__(256) void fine_attn_pool(
    const int* __restrict__ pidx, const float* __restrict__ seeds)
{
    extern __shared__ uint32_t sf[];
    uint32_t* Kr  = sf;                         // [128][68]
    uint32_t* Vr  = sf + 128 * 68;              // [64][136]
    uint32_t* qsm = sf + 128 * 68 + 64 * 136;   // [2][64] packed scaled seeds
    float*    ps  = (float*)(qsm + 128);        // [2][128] tile probabilities
    float*    rka = ps + 256;                   // [2][128] online rep-K acc
    float*    rva = rka + 256;                  // [2][128] online rep-V acc
    float*    mls = rva + 256;                  // [0,1]=m  [2,3]=l  [4,5]=corr

    const int tid = threadIdx.x, warp = tid >> 5, lane = tid & 31;
    const int lr = lane >> 2, lc = lane & 3;
    const int kpart = blockIdx.x, h = blockIdx.y, zs = blockIdx.z;
    const int* pi = pidx + kpart * SSZ;

    // ---- init pooling state + seeds ----
    if (tid < 128) {
        rka[tid] = 0.f; rka[128 + tid] = 0.f;
        rva[tid] = 0.f; rva[128 + tid] = 0.f;
        const int ml = tid >> 6, dp = tid & 63;
        const float* sp = seeds + (size_t)(zs * 2 + ml) * HD + h * DD + 2 * dp;
        qsm[ml * 64 + dp] = bf2(sp[0] * INV_SCALE, sp[1] * INV_SCALE);
    } else if (tid < 136) {
        mls[tid - 128] = (tid - 128 < 2) ? -INFINITY : 0.f;
    }

    // ---- q fragments ----
    const int wq = warp * 16;
    const int qb = zs * 128;
    const int n0g = pi[qb + wq + lr];
    const int n1g = pi[qb + wq + lr + 8];

    uint32_t qa[8][4];
    {
        const uint32_t* q0p = g_Qb + (size_t)n0g * 256 + h * 64;
        const uint32_t* q1p = g_Qb + (size_t)n1g * 256 + h * 64;
#pragma unroll
        for (int kf = 0; kf < 8; kf++) {
            qa[kf][0] = q0p[kf * 8 + lc];
            qa[kf][1] = q1p[kf * 8 + lc];
            qa[kf][2] = q0p[kf * 8 + lc + 4];
            qa[kf][3] = q1p[kf * 8 + lc + 4];
        }
    }

    float4 acc[16];
#pragma unroll
    for (int ni = 0; ni < 16; ni++) acc[ni] = make_float4(0.f, 0.f, 0.f, 0.f);
    float m0 = -INFINITY, m1 = -INFINITY, l0 = 0.f, l1 = 0.f;

#pragma unroll 1
    for (int half = 0; half < 2; half++) {
        __syncthreads();   // Kr/Vr/ps reuse + init visibility

        // ---- stage K half (128 keys, 2 thr/key) ----
        {
            const int key = tid >> 1, dh = (tid & 1) * 32;
            const int node = pi[half * 128 + key];
            const uint32_t* src = g_Kb + (size_t)node * 256 + h * 64 + dh;
            uint32_t* dst = Kr + key * 68 + dh;
#pragma unroll
            for (int j = 0; j < 8; j++)
                *(uint4*)(dst + 4 * j) = *(const uint4*)(src + 4 * j);
        }
        // ---- stage V half (64 kpairs, 4 thr/kpair, PRMT cross-pack) ----
        {
            const int kpi = tid >> 2, q4 = (tid & 3) * 16;
            const int ka = pi[half * 128 + 2 * kpi];
            const int kb = pi[half * 128 + 2 * kpi + 1];
            const uint32_t* sa = g_Vb + (size_t)ka * 256 + h * 64 + q4;
            const uint32_t* sb = g_Vb + (size_t)kb * 256 + h * 64 + q4;
            uint32_t* dst = Vr + kpi * 136 + q4 * 2;
#pragma unroll
            for (int j = 0; j < 4; j++) {
                uint4 a = *(const uint4*)(sa + 4 * j);
                uint4 b = *(const uint4*)(sb + 4 * j);
                uint4 o0, o1;
                o0.x = prmt(a.x, b.x, 0x5410); o0.y = prmt(a.x, b.x, 0x7632);
                o0.z = prmt(a.y, b.y, 0x5410); o0.w = prmt(a.y, b.y, 0x7632);
                o1.x = prmt(a.z, b.z, 0x5410); o1.y = prmt(a.z, b.z, 0x7632);
                o1.z = prmt(a.w, b.w, 0x5410); o1.w = prmt(a.w, b.w, 0x7632);
                *(uint4*)(dst + 8 * j)     = o0;
                *(uint4*)(dst + 8 * j + 4) = o1;
            }
        }
        __syncthreads();

        // ---- attention over this half: 2 subtiles of 64 keys ----
#pragma unroll 1
        for (int kt = 0; kt < 2; kt++) {
            float4 s[8];
#pragma unroll
            for (int ni = 0; ni < 8; ni++) s[ni] = make_float4(0.f, 0.f, 0.f, 0.f);
#pragma unroll
            for (int kf = 0; kf < 8; kf++) {
#pragma unroll
                for (int ni = 0; ni < 8; ni++) {
                    const uint32_t* kr = Kr + (kt * 64 + ni * 8 + lr) * 68 + kf * 8;
                    mma_bf16(s[ni], qa[kf], kr[lc], kr[lc + 4]);
                }
            }

            float tm0 = -INFINITY, tm1 = -INFINITY;
#pragma unroll
            for (int ni = 0; ni < 8; ni++) {
                tm0 = fmaxf(tm0, fmaxf(s[ni].x, s[ni].y));
                tm1 = fmaxf(tm1, fmaxf(s[ni].z, s[ni].w));
            }
            tm0 = warp_max2(tm0); tm1 = warp_max2(tm1);
            const float mn0 = fmaxf(m0, tm0), mn1 = fmaxf(m1, tm1);
            const float c0 = __expf(m0 - mn0), c1 = __expf(m1 - mn1);
            m0 = mn0; m1 = mn1;

            float rs0 = 0.f, rs1 = 0.f;
            uint32_t pa[4][4];
#pragma unroll
            for (int ni = 0; ni < 8; ni++) {
                const float p0 = __expf(s[ni].x - mn0);
                const float p1 = __expf(s[ni].y - mn0);
                const float p2 = __expf(s[ni].z - mn1);
                const float p3 = __expf(s[ni].w - mn1);
                rs0 += p0 + p1; rs1 += p2 + p3;
                pa[ni >> 1][(ni & 1) * 2 + 0] = bf2(p0, p1);
                pa[ni >> 1][(ni & 1) * 2 + 1] = bf2(p2, p3);
            }
            rs0 = warp_sum2(rs0); rs1 = warp_sum2(rs1);
            l0 = l0 * c0 + rs0; l1 = l1 * c1 + rs1;
#pragma unroll
            for (int ni = 0; ni < 16; ni++) {
                acc[ni].x *= c0; acc[ni].y *= c0;
                acc[ni].z *= c1; acc[ni].w *= c1;
            }

#pragma unroll
            for (int kf = 0; kf < 4; kf++) {
                const uint32_t* vr0 = Vr + (kt * 32 + kf * 8 + lc) * 136;
                const uint32_t* vr1 = Vr + (kt * 32 + kf * 8 + lc + 4) * 136;
#pragma unroll
                for (int ni = 0; ni < 16; ni++)
                    mma_bf16(acc[ni], pa[kf], vr0[ni * 8 + lr], vr1[ni * 8 + lr]);
            }
        }

        // ---- online pooling, this half ----
        if (warp < 2) {
            const int m = warp;
            float sc[4];
            float tmax = -INFINITY;
            const uint32_t* qm = qsm + m * 64;
#pragma unroll
            for (int j = 0; j < 4; j++) {
                const int key = j * 32 + lane;
                float s = 0.f;
                const uint32_t* kr = Kr + key * 68;
#pragma unroll
                for (int dp = 0; dp < 64; dp++) {
                    const uint32_t u = kr[dp];
                    const uint32_t qq = qm[dp];
                    s += bflo(qq) * bflo(u) + bfhi(qq) * bfhi(u);
                }
                sc[j] = s;
                tmax = fmaxf(tmax, s);
            }
            tmax = warp_max32(tmax);
            const float mold = mls[m];
            const float mnew = fmaxf(mold, tmax);
            const float corr = __expf(mold - mnew);
            float lsum = 0.f;
#pragma unroll
            for (int j = 0; j < 4; j++) {
                const float p = __expf(sc[j] - mnew);
                ps[m * 128 + j * 32 + lane] = p;
                lsum += p;
            }
            lsum = warp_sum32(lsum);
            if (lane == 0) {
                mls[m] = mnew;
                mls[2 + m] = mls[2 + m] * corr + lsum;
                mls[4 + m] = corr;
            }
        }
        __syncthreads();

        if (tid < 128) {
            const int ml = tid >> 6, dp = tid & 63;
            const float corr = mls[4 + ml];
            float rk0 = rka[ml * 128 + 2 * dp]     * corr;
            float rk1 = rka[ml * 128 + 2 * dp + 1] * corr;
            float rv0 = rva[ml * 128 + 2 * dp]     * corr;
            float rv1 = rva[ml * 128 + 2 * dp + 1] * corr;
            const float* pm = ps + ml * 128;
#pragma unroll 4
            for (int kp = 0; kp < 64; kp++) {
                const float p0 = pm[2 * kp], p1 = pm[2 * kp + 1];
                const uint32_t ka = Kr[(2 * kp) * 68 + dp];
                const uint32_t kb = Kr[(2 * kp + 1) * 68 + dp];
                rk0 += p0 * bflo(ka) + p1 * bflo(kb);
                rk1 += p0 * bfhi(ka) + p1 * bfhi(kb);
                const uint2 vv = *(const uint2*)&Vr[kp * 136 + 2 * dp];
                rv0 += p0 * bflo(vv.x) + p1 * bfhi(vv.x);
                rv1 += p0 * bflo(vv.y) + p1 * bfhi(vv.y);
            }
            rka[ml * 128 + 2 * dp]     = rk0;
            rka[ml * 128 + 2 * dp + 1] = rk1;
            rva[ml * 128 + 2 * dp]     = rv0;
            rva[ml * 128 + 2 * dp + 1] = rv1;
        }
    }

    // ---- attention write-out (registers only) ----
    {
        const float inv0 = 1.f / l0, inv1 = 1.f / l1;
        uint32_t* o0 = g_outLb + (size_t)n0g * 256 + h * 64;
        uint32_t* o1 = g_outLb + (size_t)n1g * 256 + h * 64;
#pragma unroll
        for (int ni = 0; ni < 16; ni++) {
            o0[ni * 4 + lc] = bf2(acc[ni].x * inv0, acc[ni].y * inv0);
            o1[ni * 4 + lc] = bf2(acc[ni].z * inv1, acc[ni].w * inv1);
        }
    }

    // ---- pooling write-out ----
    __syncthreads();
    if (tid < 128) {
        const int ml = tid >> 6, dp = tid & 63;
        const float inv = 1.f / mls[2 + ml];
        const int r = kpart * MM + zs * 2 + ml;
        g_repKb[(size_t)r * 256 + h * 64 + dp] =
            bf2(rka[ml * 128 + 2 * dp] * inv, rka[ml * 128 + 2 * dp + 1] * inv);
        rva[ml * 128 + 2 * dp]     *= inv;
        rva[ml * 128 + 2 * dp + 1] *= inv;
    }
    __syncthreads();
    if (tid < 128) {
        const int rpair = kpart * 2 + zs;
        g_repVb2[(size_t)rpair * 512 + h * 128 + tid] =
            bf2(rva[tid], rva[128 + tid]);
    }
}

// ---------------------------------------------------------------------------
// Kernel 3: global cross-attention; cp.async double-buffered K/V tiles.
// ---------------------------------------------------------------------------
#define GA_BUF 8704
#define GA_SMEM_BYTES (2 * GA_BUF * 4)

__global__ __launch_bounds__(256) void global_attn()
{
    extern __shared__ uint32_t sg[];

    const int tid = threadIdx.x, warp = tid >> 5, lane = tid & 31;
    const int lr = lane >> 2, lc = lane & 3;
    const int h = blockIdx.y;
    const int q0 = blockIdx.x * 128;
    const int wq = warp * 16;
    const int n0g = q0 + wq + lr, n1g = q0 + wq + lr + 8;
    const uint32_t sbase = smem_u32addr(sg);

    auto issueG = [&](int t, int b) {
        const uint32_t base = sbase + b * GA_BUF * 4;
#pragma unroll
        for (int j = 0; j < 8; j++) {
            const int cid = tid * 8 + j;
            if (cid < 1024) {
                const int row = cid >> 4, c4 = (cid & 15) * 4;
                CP_ASYNC16(base + (row * 68 + c4) * 4,
                           g_repKb + (size_t)(t + row) * 256 + h * 64 + c4);
            } else {
                const int cid2 = cid - 1024;
                const int kpi = cid2 >> 5, c4 = (cid2 & 31) * 4;
                CP_ASYNC16(base + (64 * 68 + kpi * 136 + c4) * 4,
                           g_repVb2 + (size_t)((t >> 1) + kpi) * 512 + h * 128 + c4);
            }
        }
    };

    uint32_t qa[8][4];
    {
        const uint32_t* q0p = g_Qb + (size_t)n0g * 256 + h * 64;
        const uint32_t* q1p = g_Qb + (size_t)n1g * 256 + h * 64;
#pragma unroll
        for (int kf = 0; kf < 8; kf++) {
            qa[kf][0] = q0p[kf * 8 + lc];
            qa[kf][1] = q1p[kf * 8 + lc];
            qa[kf][2] = q0p[kf * 8 + lc + 4];
            qa[kf][3] = q1p[kf * 8 + lc + 4];
        }
    }

    float4 acc[16];
#pragma unroll
    for (int ni = 0; ni < 16; ni++) acc[ni] = make_float4(0.f, 0.f, 0.f, 0.f);
    float m0 = -INFINITY, m1 = -INFINITY, l0 = 0.f, l1 = 0.f;

    issueG(0, 0);  CP_COMMIT();
    issueG(64, 1); CP_COMMIT();

    for (int ti = 0; ti < 8; ti++) {
        if (ti < 7) CP_WAIT(1); else CP_WAIT(0);
        __syncthreads();

        const uint32_t* Kr = sg + (ti & 1) * GA_BUF;
        const uint32_t* Vr = Kr + 64 * 68;

        float4 s[8];
#pragma unroll
        for (int ni = 0; ni < 8; ni++) s[ni] = make_float4(0.f, 0.f, 0.f, 0.f);
#pragma unroll
        for (int kf = 0; kf < 8; kf++) {
#pragma unroll
            for (int ni = 0; ni < 8; ni++) {
                const uint32_t* kr = Kr + (ni * 8 + lr) * 68 + kf * 8;
                mma_bf16(s[ni], qa[kf], kr[lc], kr[lc + 4]);
            }
        }

        float tm0 = -INFINITY, tm1 = -INFINITY;
#pragma unroll
        for (int ni = 0; ni < 8; ni++) {
            tm0 = fmaxf(tm0, fmaxf(s[ni].x, s[ni].y));
            tm1 = fmaxf(tm1, fmaxf(s[ni].z, s[ni].w));
        }
        tm0 = warp_max2(tm0); tm1 = warp_max2(tm1);
        const float mn0 = fmaxf(m0, tm0), mn1 = fmaxf(m1, tm1);
        const float c0 = __expf(m0 - mn0), c1 = __expf(m1 - mn1);
        m0 = mn0; m1 = mn1;

        float rs0 = 0.f, rs1 = 0.f;
        uint32_t pa[4][4];
#pragma unroll
        for (int ni = 0; ni < 8; ni++) {
            const float p0 = __expf(s[ni].x - mn0);
            const float p1 = __expf(s[ni].y - mn0);
            const float p2 = __expf(s[ni].z - mn1);
            const float p3 = __expf(s[ni].w - mn1);
            rs0 += p0 + p1; rs1 += p2 + p3;
            pa[ni >> 1][(ni & 1) * 2 + 0] = bf2(p0, p1);
            pa[ni >> 1][(ni & 1) * 2 + 1] = bf2(p2, p3);
        }
        rs0 = warp_sum2(rs0); rs1 = warp_sum2(rs1);
        l0 = l0 * c0 + rs0; l1 = l1 * c1 + rs1;
#pragma unroll
        for (int ni = 0; ni < 16; ni++) {
            acc[ni].x *= c0; acc[ni].y *= c0;
            acc[ni].z *= c1; acc[ni].w *= c1;
        }

#pragma unroll
        for (int kf = 0; kf < 4; kf++) {
            const uint32_t* vr0 = Vr + (kf * 8 + lc) * 136;
            const uint32_t* vr1 = Vr + (kf * 8 + lc + 4) * 136;
#pragma unroll
            for (int ni = 0; ni < 16; ni++)
                mma_bf16(acc[ni], pa[kf], vr0[ni * 8 + lr], vr1[ni * 8 + lr]);
        }

        __syncthreads();
        if (ti + 2 < 8) { issueG((ti + 2) * 64, ti & 1); CP_COMMIT(); }
    }

    const float inv0 = 1.f / l0, inv1 = 1.f / l1;
    uint32_t* o0 = g_outGb + (size_t)n0g * 256 + h * 64;
    uint32_t* o1 = g_outGb + (size_t)n1g * 256 + h * 64;
#pragma unroll
    for (int ni = 0; ni < 16; ni++) {
        o0[ni * 4 + lc] = bf2(acc[ni].x * inv0, acc[ni].y * inv0);
        o1[ni * 4 + lc] = bf2(acc[ni].z * inv1, acc[ni].w * inv1);
    }
}

// ---------------------------------------------------------------------------
// Kernel 4: combine — unpack bf16 outL/outG, add exact x_self
// ---------------------------------------------------------------------------
__global__ __launch_bounds__(256) void combine(const float* __restrict__ alpha_logit,
                                               const float* __restrict__ beta_p,
                                               float* __restrict__ out)
{
    const int idx = blockIdx.x * 256 + threadIdx.x;
    const int n = idx >> 4, g = idx & 15;

    const float alpha = 1.f / (1.f + __expf(-alpha_logit[0]));
    const float beta  = beta_p[0];
    const float ca = alpha * 0.25f;
    const float cg = (1.f - alpha) * 0.25f;

    float s[8];
#pragma unroll
    for (int j = 0; j < 8; j++) s[j] = 0.f;

#pragma unroll
    for (int h = 0; h < HH; h++) {
        const size_t base = (size_t)n * 256 + h * 64 + g * 4;
        const uint4 a = *(const uint4*)&g_outLb[base];
        const uint4 b = *(const uint4*)&g_outGb[base];
        s[0] += ca * bflo(a.x) + cg * bflo(b.x);
        s[1] += ca * bfhi(a.x) + cg * bfhi(b.x);
        s[2] += ca * bflo(a.y) + cg * bflo(b.y);
        s[3] += ca * bfhi(a.y) + cg * bfhi(b.y);
        s[4] += ca * bflo(a.z) + cg * bflo(b.z);
        s[5] += ca * bfhi(a.z) + cg * bfhi(b.z);
        s[6] += ca * bflo(a.w) + cg * bflo(b.w);
        s[7] += ca * bfhi(a.w) + cg * bfhi(b.w);
    }

    const size_t ob = (size_t)n * DD + g * 8;
    const float4 xs0 = *(const float4*)&g_xself[ob];
    const float4 xs1 = *(const float4*)&g_xself[ob + 4];
    float4 o0, o1;
    o0.x = s[0] + beta * xs0.x; o0.y = s[1] + beta * xs0.y;
    o0.z = s[2] + beta * xs0.z; o0.w = s[3] + beta * xs0.w;
    o1.x = s[4] + beta * xs1.x; o1.y = s[5] + beta * xs1.y;
    o1.z = s[6] + beta * xs1.z; o1.w = s[7] + beta * xs1.w;
    *(float4*)&out[ob]     = o0;
    *(float4*)&out[ob + 4] = o1;
}

// ---------------------------------------------------------------------------
// Launcher
// ---------------------------------------------------------------------------
extern "C" void kernel_launch(void* const* d_in, const int* in_sizes, int n_in,
                              void* d_out, int out_size)
{
    (void)in_sizes; (void)n_in; (void)out_size;
    const float* x     = (const float*)d_in[0];
    const int*   pidx  = (const int*)  d_in[1];
    const float* Wq    = (const float*)d_in[2];
    const float* bq    = (const float*)d_in[3];
    const float* Wk    = (const float*)d_in[4];
    const float* bk    = (const float*)d_in[5];
    const float* Wv    = (const float*)d_in[6];
    const float* bv    = (const float*)d_in[7];
    const float* seeds = (const float*)d_in[8];
    const float* alog  = (const float*)d_in[9];
    const float* beta  = (const float*)d_in[10];
    float* out = (float*)d_out;

    const int gxsb = 2 * 4 * GSTG * 4;

    // idempotent host-state calls; capture-legal
    cudaFuncSetAttribute((const void*)qkv_gemm_tc,
                         cudaFuncAttributeMaxDynamicSharedMemorySize, GEMM_SMEM_BYTES);
    cudaFuncSetAttribute((const void*)xself_gemm,
                         cudaFuncAttributeMaxDynamicSharedMemorySize, gxsb);
    cudaFuncSetAttribute((const void*)fine_attn_pool,
                         cudaFuncAttributeMaxDynamicSharedMemorySize, FINE_SMEM_BYTES);
    cudaFuncSetAttribute((const void*)global_attn,
                         cudaFuncAttributeMaxDynamicSharedMemorySize, GA_SMEM_BYTES);

    split_xt<<<NN / 128, 256>>>(x);
    dim3 gw(128 * HD / 256, 3);
    split_w<<<gw, 256>>>(Wq, Wk, Wv);
    wavg_split<<<64, 256>>>(Wv);

    dim3 g1(HD / 128, NN / 64);                // 64-row slabs: 4 x 512
    qkv_gemm_tc<<<g1, 256, GEMM_SMEM_BYTES>>>(bq, bk, bv);

    xself_gemm<<<NN / 128, 256, gxsb>>>(bv);   // exact x_self

    dim3 g2(KPP, HH, 2);                       // fine + pooling
    fine_attn_pool<<<g2, 256, FINE_SMEM_BYTES>>>(pidx, seeds);

    dim3 g4(NN / 128, HH);                     // global
    global_attn<<<g4, 256, GA_SMEM_BYTES>>>();

    combine<<<(NN * 16) / 256, 256>>>(alog, beta, out);
}

// round 15
// speedup vs baseline: 1.0777x; 1.0777x over previous
#include <cuda_runtime.h>
#include <cuda_bf16.h>
#include <math.h>
#include <stdint.h>

// ---------------------------------------------------------------------------
// Problem constants
// ---------------------------------------------------------------------------
#define NN   32768
#define IN_C 256
#define DD   128
#define HH   4
#define HD   512
#define MM   4
#define KPP  128
#define SSZ  256
#define RR   (KPP*MM)
#define INV_SCALE 0.088388347648318447f   // 1/sqrt(128)

// ---------------------------------------------------------------------------
// Scratch (static device globals; no allocation allowed)
// ---------------------------------------------------------------------------
__device__ float    g_xself[(size_t)NN*DD];      // exact fp32 x_self
__device__ uint32_t g_outLb[(size_t)NN*256];     // packed bf16x2 attention outs
__device__ uint32_t g_outGb[(size_t)NN*256];
__device__ uint32_t g_Qb[(size_t)NN*256];        // packed bf16x2, pre-scaled
__device__ uint32_t g_Kb[(size_t)NN*256];
__device__ uint32_t g_Vb[(size_t)NN*256];
__device__ uint32_t g_repKb[(size_t)RR*256];     // [rep][h*64+dp]
__device__ uint32_t g_repVb2[(size_t)(RR/2)*512];// [rpair][h*128+d] cross-packed
// GEMM operands
__device__ uint32_t g_xh_t[(size_t)128*NN];      // [kp][m] hi (transposed)
__device__ uint32_t g_xl_t[(size_t)128*NN];      // [kp][m] lo
__device__ uint32_t g_Wh[3][(IN_C/2)*HD];        // [kp][n] hi
__device__ uint32_t g_Wah[128*128];              // Wv head-avg hi  [kp][d]
__device__ uint32_t g_Wal[128*128];              // Wv head-avg lo

// ---------------------------------------------------------------------------
// helpers
// ---------------------------------------------------------------------------
__device__ __forceinline__ float bfr(float v) {
    return __bfloat162float(__float2bfloat16(v));
}
__device__ __forceinline__ uint32_t bf2(float lo, float hi) {
    uint32_t r;
    asm("cvt.rn.bf16x2.f32 %0, %1, %2;" : "=r"(r) : "f"(hi), "f"(lo));
    return r;
}
__device__ __forceinline__ float bflo(uint32_t u) { return __uint_as_float(u << 16); }
__device__ __forceinline__ float bfhi(uint32_t u) { return __uint_as_float(u & 0xffff0000u); }
__device__ __forceinline__ uint32_t prmt(uint32_t a, uint32_t b, uint32_t sel) {
    uint32_t r;
    asm("prmt.b32 %0, %1, %2, %3;" : "=r"(r) : "r"(a), "r"(b), "r"(sel));
    return r;
}
__device__ __forceinline__ void mma_bf16(float4& d, const uint32_t a[4],
                                         uint32_t b0, uint32_t b1) {
    asm volatile(
        "mma.sync.aligned.m16n8k16.row.col.f32.bf16.bf16.f32 "
        "{%0,%1,%2,%3}, {%4,%5,%6,%7}, {%8,%9}, {%0,%1,%2,%3};"
        : "+f"(d.x), "+f"(d.y), "+f"(d.z), "+f"(d.w)
        : "r"(a[0]), "r"(a[1]), "r"(a[2]), "r"(a[3]), "r"(b0), "r"(b1));
}
#define CP_ASYNC16(dst, src) \
    asm volatile("cp.async.cg.shared.global [%0], [%1], 16;" :: "r"(dst), "l"(src))
#define CP_COMMIT() asm volatile("cp.async.commit_group;")
#define CP_WAIT(n)  asm volatile("cp.async.wait_group %0;" :: "n"(n))

__device__ __forceinline__ uint32_t smem_u32addr(const void* p) {
    uint32_t a;
    asm("{ .reg .u64 t; cvta.to.shared.u64 t, %1; cvt.u32.u64 %0, t; }"
        : "=r"(a) : "l"(p));
    return a;
}

__device__ __forceinline__ float warp_max2(float s) {
    s = fmaxf(s, __shfl_xor_sync(0xffffffffu, s, 1));
    s = fmaxf(s, __shfl_xor_sync(0xffffffffu, s, 2));
    return s;
}
__device__ __forceinline__ float warp_sum2(float s) {
    s += __shfl_xor_sync(0xffffffffu, s, 1);
    s += __shfl_xor_sync(0xffffffffu, s, 2);
    return s;
}
__device__ __forceinline__ float warp_max32(float s) {
#pragma unroll
    for (int o = 16; o > 0; o >>= 1) s = fmaxf(s, __shfl_xor_sync(0xffffffffu, s, o));
    return s;
}
__device__ __forceinline__ float warp_sum32(float s) {
#pragma unroll
    for (int o = 16; o > 0; o >>= 1) s += __shfl_xor_sync(0xffffffffu, s, o);
    return s;
}

// ---------------------------------------------------------------------------
// split_xt: x -> transposed hi/lo bf16x2 splits  g_x{h,l}_t [kp][m]
// ---------------------------------------------------------------------------
__global__ __launch_bounds__(256) void split_xt(const float* __restrict__ x)
{
    __shared__ uint32_t Th[32][132];
    __shared__ uint32_t Tl[32][132];
    const int m0 = blockIdx.x * 128;
    const int tid = threadIdx.x;
#pragma unroll
    for (int c = 0; c < 4; c++) {
        const int kpb = c * 32;
        {
            const int m = tid >> 1, half = tid & 1;
            const float* src = x + (size_t)(m0 + m) * IN_C + (kpb + half * 16) * 2;
#pragma unroll
            for (int j = 0; j < 16; j++) {
                float2 v = *(const float2*)(src + 2 * j);
                const float h0 = bfr(v.x), h1 = bfr(v.y);
                Th[half * 16 + j][m] = bf2(v.x, v.y);
                Tl[half * 16 + j][m] = bf2(v.x - h0, v.y - h1);
            }
        }
        __syncthreads();
        {
            const int kpr = tid >> 3, mo = (tid & 7) * 16;
            uint32_t* dh = g_xh_t + (size_t)(kpb + kpr) * NN + m0 + mo;
            uint32_t* dl = g_xl_t + (size_t)(kpb + kpr) * NN + m0 + mo;
#pragma unroll
            for (int j = 0; j < 4; j++) {
                *(uint4*)(dh + 4 * j) = *(uint4*)&Th[kpr][mo + 4 * j];
                *(uint4*)(dl + 4 * j) = *(uint4*)&Tl[kpr][mo + 4 * j];
            }
        }
        __syncthreads();
    }
}

// ---------------------------------------------------------------------------
// split_w: W -> hi bf16x2  g_Wh [kp][n]
// ---------------------------------------------------------------------------
__global__ __launch_bounds__(256) void split_w(
    const float* __restrict__ Wq, const float* __restrict__ Wk,
    const float* __restrict__ Wv)
{
    const float* W = (blockIdx.y == 0) ? Wq : (blockIdx.y == 1) ? Wk : Wv;
    const int idx = blockIdx.x * 256 + threadIdx.x;
    const int kp = idx >> 9, n = idx & 511;
    const float v0 = W[(size_t)(2 * kp) * HD + n];
    const float v1 = W[(size_t)(2 * kp + 1) * HD + n];
    g_Wh[blockIdx.y][idx] = bf2(v0, v1);
}

// ---------------------------------------------------------------------------
// wavg_split: Wavg[k][d] = mean_h Wv[k][h*128+d], hi/lo split
// ---------------------------------------------------------------------------
__global__ __launch_bounds__(256) void wavg_split(const float* __restrict__ Wv)
{
    const int idx = blockIdx.x * 256 + threadIdx.x;
    const int kp = idx >> 7, d = idx & 127;
    const float* r0 = Wv + (size_t)(2 * kp) * HD;
    const float* r1 = Wv + (size_t)(2 * kp + 1) * HD;
    const float v0 = 0.25f * (r0[d] + r0[128 + d] + r0[256 + d] + r0[384 + d]);
    const float v1 = 0.25f * (r1[d] + r1[128 + d] + r1[256 + d] + r1[384 + d]);
    const float h0 = bfr(v0), h1 = bfr(v1);
    g_Wah[idx] = bf2(v0, v1);
    g_Wal[idx] = bf2(v0 - h0, v1 - h1);
}

// ---------------------------------------------------------------------------
// Kernel 1: unified A-resident QKV GEMM (R12 config — measured at ~88% of the
// mma.sync HMMA roofline; do not touch). Block = 128-row x 128-col slab;
// full-K A resident; z looped; B via 4-deep cp.async ring. 2M x 4N warps.
// ---------------------------------------------------------------------------
#define GSTG 2176                        // 16*136 u32 per B stage
#define ASMEM (128 * 136)                // full-K A tile
#define GEMM_SMEM_BYTES ((ASMEM + 4 * GSTG) * 4)

__global__ __launch_bounds__(256) void qkv_gemm_tc(
    const float* __restrict__ bq, const float* __restrict__ bk,
    const float* __restrict__ bv)
{
    extern __shared__ uint32_t smg[];
    uint32_t* Asm = smg;                 // [128 kp][136 m]
    uint32_t* Bbuf = smg + ASMEM;        // 4 x [16 kp][136 n]

    const int tid  = threadIdx.x;
    const int warp = tid >> 5, lane = tid & 31;
    const int lr = lane >> 2, lc = lane & 3;
    const int wm = warp & 1, wn = warp >> 1;    // 2M x 4N warp grid
    const int row0 = blockIdx.y * 128;
    const int col0 = blockIdx.x * 128;

    {
        const uint32_t abase = smem_u32addr(Asm);
#pragma unroll
        for (int j = 0; j < 16; j++) {
            const int cid = j * 256 + tid;
            const int kpr = cid >> 5, f = (cid & 31) * 4;
            CP_ASYNC16(abase + (kpr * 136 + f) * 4,
                       g_xh_t + (size_t)kpr * NN + row0 + f);
        }
        CP_COMMIT();
    }

    auto issueB = [&](int st) {
        const int z = st >> 3, kp0 = (st & 7) * 16;
        const uint32_t base = smem_u32addr(Bbuf + (st & 3) * GSTG);
        const uint32_t* WH = g_Wh[z];
#pragma unroll
        for (int j = 0; j < 2; j++) {
            const int slot = tid * 2 + j;
            const int kpr = slot >> 5, f = (slot & 31) * 4;
            CP_ASYNC16(base + (kpr * 136 + f) * 4,
                       WH + (size_t)(kp0 + kpr) * HD + col0 + f);
        }
        CP_COMMIT();
    };

    issueB(0); issueB(1); issueB(2); issueB(3);

    float4 acc[4][4];                    // 64m x 32n warp tile
#pragma unroll
    for (int mi = 0; mi < 4; mi++)
#pragma unroll
        for (int ni = 0; ni < 4; ni++)
            acc[mi][ni] = make_float4(0.f, 0.f, 0.f, 0.f);

#pragma unroll 1
    for (int st = 0; st < 24; st++) {
        if (st < 21)      CP_WAIT(3);
        else if (st == 21) CP_WAIT(2);
        else if (st == 22) CP_WAIT(1);
        else               CP_WAIT(0);
        __syncthreads();

        const uint32_t* Bh = Bbuf + (st & 3) * GSTG;
        const int ks = (st & 7) * 16;

#pragma unroll
        for (int kf = 0; kf < 2; kf++) {
            const int ra0 = (ks + kf * 8 + lc) * 136;
            const int ra1 = (ks + kf * 8 + lc + 4) * 136;
            const int rb0 = (kf * 8 + lc) * 136;
            const int rb1 = (kf * 8 + lc + 4) * 136;
            uint32_t ah[4][4];
#pragma unroll
            for (int mi = 0; mi < 4; mi++) {
                const int m0 = wm * 64 + mi * 16 + lr;
                ah[mi][0] = Asm[ra0 + m0]; ah[mi][1] = Asm[ra0 + m0 + 8];
                ah[mi][2] = Asm[ra1 + m0]; ah[mi][3] = Asm[ra1 + m0 + 8];
            }
#pragma unroll
            for (int ni = 0; ni < 4; ni++) {
                const int n0 = wn * 32 + ni * 8 + lr;
                const uint32_t bh0 = Bh[rb0 + n0], bh1 = Bh[rb1 + n0];
#pragma unroll
                for (int mi = 0; mi < 4; mi++)
                    mma_bf16(acc[mi][ni], ah[mi], bh0, bh1);
            }
        }

        if ((st & 7) == 7) {
            const int z = st >> 3;
            const float* bias = (z == 0) ? bq : (z == 1) ? bk : bv;
            uint32_t* Cb = (z == 0) ? g_Qb : (z == 1) ? g_Kb : g_Vb;
#pragma unroll
            for (int mi = 0; mi < 4; mi++) {
                const int r = row0 + wm * 64 + mi * 16 + lr;
#pragma unroll
                for (int ni = 0; ni < 4; ni++) {
                    const int c = col0 + wn * 32 + ni * 8 + 2 * lc;
                    const float2 b2 = *(const float2*)&bias[c];
                    float x0 = acc[mi][ni].x + b2.x, y0 = acc[mi][ni].y + b2.y;
                    float x1 = acc[mi][ni].z + b2.x, y1 = acc[mi][ni].w + b2.y;
                    if (z == 0) { x0 *= INV_SCALE; y0 *= INV_SCALE;
                                  x1 *= INV_SCALE; y1 *= INV_SCALE; }
                    const int cp = c >> 1;
                    Cb[(size_t)r * 256 + cp]       = bf2(x0, y0);
                    Cb[(size_t)(r + 8) * 256 + cp] = bf2(x1, y1);
                    acc[mi][ni] = make_float4(0.f, 0.f, 0.f, 0.f);
                }
            }
        }

        __syncthreads();
        if (st + 4 < 24) issueB(st + 4);
    }
}

// ---------------------------------------------------------------------------
// Kernel 1b: exact x_self GEMM (M=NN, K=256, N=128), 3-term bf16 split
// ---------------------------------------------------------------------------
__global__ __launch_bounds__(256) void xself_gemm(const float* __restrict__ bv)
{
    extern __shared__ uint32_t smx[];

    const int tid  = threadIdx.x;
    const int warp = tid >> 5, lane = tid & 31;
    const int lr = lane >> 2, lc = lane & 3;
    const int wm = warp & 1, wn = warp >> 1;    // 2M x 4N
    const int row0 = blockIdx.x * 128;

    auto issue = [&](int it, int b) {
        const int kp0 = it * 16;
        const uint32_t base = smem_u32addr(smx + b * 4 * GSTG);
#pragma unroll
        for (int j = 0; j < 2; j++) {
            const int slot = tid * 2 + j;
            const int kpr = slot >> 5, f = (slot & 31) * 4;
            const uint32_t doff = (kpr * 136 + f) * 4;
            const size_t asrc = (size_t)(kp0 + kpr) * NN + row0 + f;
            const size_t bsrc = (size_t)(kp0 + kpr) * 128 + f;
            CP_ASYNC16(base + 0 * GSTG * 4 + doff, g_xh_t + asrc);
            CP_ASYNC16(base + 1 * GSTG * 4 + doff, g_xl_t + asrc);
            CP_ASYNC16(base + 2 * GSTG * 4 + doff, g_Wah + bsrc);
            CP_ASYNC16(base + 3 * GSTG * 4 + doff, g_Wal + bsrc);
        }
    };

    float4 acc[4][4];
#pragma unroll
    for (int mi = 0; mi < 4; mi++)
#pragma unroll
        for (int ni = 0; ni < 4; ni++)
            acc[mi][ni] = make_float4(0.f, 0.f, 0.f, 0.f);

    issue(0, 0); CP_COMMIT();

    for (int it = 0; it < 8; it++) {
        if (it < 7) { issue(it + 1, (it + 1) & 1); CP_COMMIT(); CP_WAIT(1); }
        else        { CP_WAIT(0); }
        __syncthreads();

        const uint32_t* buf = smx + (it & 1) * 4 * GSTG;
        const uint32_t* Ah = buf;
        const uint32_t* Al = buf + GSTG;
        const uint32_t* Bh = buf + 2 * GSTG;
        const uint32_t* Bl = buf + 3 * GSTG;

#pragma unroll
        for (int kf = 0; kf < 2; kf++) {
            const int r0 = (kf * 8 + lc) * 136;
            const int r1 = (kf * 8 + lc + 4) * 136;
            uint32_t ah[4][4], al[4][4];
#pragma unroll
            for (int mi = 0; mi < 4; mi++) {
                const int m0 = wm * 64 + mi * 16 + lr;
                ah[mi][0] = Ah[r0 + m0]; ah[mi][1] = Ah[r0 + m0 + 8];
                ah[mi][2] = Ah[r1 + m0]; ah[mi][3] = Ah[r1 + m0 + 8];
                al[mi][0] = Al[r0 + m0]; al[mi][1] = Al[r0 + m0 + 8];
                al[mi][2] = Al[r1 + m0]; al[mi][3] = Al[r1 + m0 + 8];
            }
#pragma unroll
            for (int ni = 0; ni < 4; ni++) {
                const int n0 = wn * 32 + ni * 8 + lr;
                const uint32_t bh0 = Bh[r0 + n0], bh1 = Bh[r1 + n0];
                const uint32_t bl0 = Bl[r0 + n0], bl1 = Bl[r1 + n0];
#pragma unroll
                for (int mi = 0; mi < 4; mi++) {
                    mma_bf16(acc[mi][ni], ah[mi], bh0, bh1);
                    mma_bf16(acc[mi][ni], ah[mi], bl0, bl1);
                    mma_bf16(acc[mi][ni], al[mi], bh0, bh1);
                }
            }
        }
        __syncthreads();
    }

#pragma unroll
    for (int mi = 0; mi < 4; mi++) {
        const int r = row0 + wm * 64 + mi * 16 + lr;
#pragma unroll
        for (int ni = 0; ni < 4; ni++) {
            const int c = wn * 32 + ni * 8 + 2 * lc;
            const float bx = 0.25f * (bv[c] + bv[128 + c] + bv[256 + c] + bv[384 + c]);
            const float by = 0.25f * (bv[c+1] + bv[129 + c] + bv[257 + c] + bv[385 + c]);
            *(float2*)&g_xself[(size_t)r * DD + c] =
                make_float2(acc[mi][ni].x + bx, acc[mi][ni].y + by);
            *(float2*)&g_xself[(size_t)(r + 8) * DD + c] =
                make_float2(acc[mi][ni].z + bx, acc[mi][ni].w + by);
        }
    }
}

// ---------------------------------------------------------------------------
// Kernel 2: fine attention (z-split) + coarse pooling.
// K fully RESIDENT (256 keys, 69.6 KB); V streamed in two 64-kpair halves
// (34.8 KB) -> total ~108 KB -> 2 blocks/SM. Pooling scores computed once on
// resident K (exact softmax); rep-V accumulation follows V halves.
//   Kr [256][68] | Vr [64][136] | qsm u32[2][64] | ps f[2][256]
//   rva f[2][128] | lsm f[2]
// ---------------------------------------------------------------------------
#define FINE_SMEM_U32 (256*68 + 64*136 + 128 + 512 + 256 + 8)
#define FINE_SMEM_BYTES (FINE_SMEM_U32 * 4)

__global__ __launch_bounds__(256) void fine_attn_pool(
    const int* __restrict__ pidx, const float* __restrict__ seeds)
{
    extern __shared__ uint32_t sf[];
    uint32_t* Kr  = sf;                          // [256][68]
    uint32_t* Vr  = sf + 256 * 68;               // [64][136]
    uint32_t* qsm = sf + 256 * 68 + 64 * 136;    // [2][64]
    float*    ps  = (float*)(qsm + 128);         // [2][256]
    float*    rva = ps + 512;                    // [2][128]
    float*    lsm = rva + 256;                   // [2]

    const int tid = threadIdx.x, warp = tid >> 5, lane = tid & 31;
    const int lr = lane >> 2, lc = lane & 3;
    const int kpart = blockIdx.x, h = blockIdx.y, zs = blockIdx.z;
    const int* pi = pidx + kpart * SSZ;

    // ---- stage K full (one key per thread) ----
    {
        const int node = pi[tid];
        const uint32_t* src = g_Kb + (size_t)node * 256 + h * 64;
        uint32_t* dst = Kr + tid * 68;
#pragma unroll
        for (int j = 0; j < 16; j++)
            *(uint4*)(dst + 4 * j) = *(const uint4*)(src + 4 * j);
    }
    // ---- stage V half 0 (64 kpairs, 4 thr/kpair, PRMT cross-pack) ----
    auto stageV = [&](int vh) {
        const int kpi = tid >> 2, q4 = (tid & 3) * 16;
        const int ka = pi[vh * 128 + 2 * kpi];
        const int kb = pi[vh * 128 + 2 * kpi + 1];
        const uint32_t* sa = g_Vb + (size_t)ka * 256 + h * 64 + q4;
        const uint32_t* sb = g_Vb + (size_t)kb * 256 + h * 64 + q4;
        uint32_t* dst = Vr + kpi * 136 + q4 * 2;
#pragma unroll
        for (int j = 0; j < 4; j++) {
            uint4 a = *(const uint4*)(sa + 4 * j);
            uint4 b = *(const uint4*)(sb + 4 * j);
            uint4 o0, o1;
            o0.x = prmt(a.x, b.x, 0x5410); o0.y = prmt(a.x, b.x, 0x7632);
            o0.z = prmt(a.y, b.y, 0x5410); o0.w = prmt(a.y, b.y, 0x7632);
            o1.x = prmt(a.z, b.z, 0x5410); o1.y = prmt(a.z, b.z, 0x7632);
            o1.z = prmt(a.w, b.w, 0x5410); o1.w = prmt(a.w, b.w, 0x7632);
            *(uint4*)(dst + 8 * j)     = o0;
            *(uint4*)(dst + 8 * j + 4) = o1;
        }
    };
    stageV(0);
    // seeds + rep-V accumulator init
    if (tid < 128) {
        rva[tid] = 0.f; rva[128 + tid] = 0.f;
        const int ml = tid >> 6, dp = tid & 63;
        const float* sp = seeds + (size_t)(zs * 2 + ml) * HD + h * DD + 2 * dp;
        qsm[ml * 64 + dp] = bf2(sp[0] * INV_SCALE, sp[1] * INV_SCALE);
    }
    __syncthreads();

    // ---- raw pooling scores on resident K (all 8 warps, 2 keys/lane) ----
    {
        const int m = warp >> 2, kb = warp & 3;
        const uint32_t* qm = qsm + m * 64;
#pragma unroll
        for (int j = 0; j < 2; j++) {
            const int key = kb * 64 + j * 32 + lane;
            float s = 0.f;
            const uint32_t* kr = Kr + key * 68;
#pragma unroll
            for (int dp = 0; dp < 64; dp++) {
                const uint32_t u = kr[dp];
                const uint32_t qq = qm[dp];
                s += bflo(qq) * bflo(u) + bfhi(qq) * bfhi(u);
            }
            ps[m * 256 + key] = s;
        }
    }

    // ---- q fragments ----
    const int wq = warp * 16;
    const int qb = zs * 128;
    const int n0g = pi[qb + wq + lr];
    const int n1g = pi[qb + wq + lr + 8];

    uint32_t qa[8][4];
    {
        const uint32_t* q0p = g_Qb + (size_t)n0g * 256 + h * 64;
        const uint32_t* q1p = g_Qb + (size_t)n1g * 256 + h * 64;
#pragma unroll
        for (int kf = 0; kf < 8; kf++) {
            qa[kf][0] = q0p[kf * 8 + lc];
            qa[kf][1] = q1p[kf * 8 + lc];
            qa[kf][2] = q0p[kf * 8 + lc + 4];
            qa[kf][3] = q1p[kf * 8 + lc + 4];
        }
    }

    float4 acc[16];
#pragma unroll
    for (int ni = 0; ni < 16; ni++) acc[ni] = make_float4(0.f, 0.f, 0.f, 0.f);
    float m0 = -INFINITY, m1 = -INFINITY, l0 = 0.f, l1 = 0.f;

#pragma unroll 1
    for (int vh = 0; vh < 2; vh++) {
        if (vh == 1) {
            __syncthreads();        // repV half0 done reading Vr
            stageV(1);
            __syncthreads();
        }

        // ---- attention over 2 key subtiles of this half ----
#pragma unroll 1
        for (int kt2 = 0; kt2 < 2; kt2++) {
            const int kbase = vh * 128 + kt2 * 64;
            float4 s[8];
#pragma unroll
            for (int ni = 0; ni < 8; ni++) s[ni] = make_float4(0.f, 0.f, 0.f, 0.f);
#pragma unroll
            for (int kf = 0; kf < 8; kf++) {
#pragma unroll
                for (int ni = 0; ni < 8; ni++) {
                    const uint32_t* kr = Kr + (kbase + ni * 8 + lr) * 68 + kf * 8;
                    mma_bf16(s[ni], qa[kf], kr[lc], kr[lc + 4]);
                }
            }

            float tm0 = -INFINITY, tm1 = -INFINITY;
#pragma unroll
            for (int ni = 0; ni < 8; ni++) {
                tm0 = fmaxf(tm0, fmaxf(s[ni].x, s[ni].y));
                tm1 = fmaxf(tm1, fmaxf(s[ni].z, s[ni].w));
            }
            tm0 = warp_max2(tm0); tm1 = warp_max2(tm1);
            const float mn0 = fmaxf(m0, tm0), mn1 = fmaxf(m1, tm1);
            const float c0 = __expf(m0 - mn0), c1 = __expf(m1 - mn1);
            m0 = mn0; m1 = mn1;

            float rs0 = 0.f, rs1 = 0.f;
            uint32_t pa[4][4];
#pragma unroll
            for (int ni = 0; ni < 8; ni++) {
                const float p0 = __expf(s[ni].x - mn0);
                const float p1 = __expf(s[ni].y - mn0);
                const float p2 = __expf(s[ni].z - mn1);
                const float p3 = __expf(s[ni].w - mn1);
                rs0 += p0 + p1; rs1 += p2 + p3;
                pa[ni >> 1][(ni & 1) * 2 + 0] = bf2(p0, p1);
                pa[ni >> 1][(ni & 1) * 2 + 1] = bf2(p2, p3);
            }
            rs0 = warp_sum2(rs0); rs1 = warp_sum2(rs1);
            l0 = l0 * c0 + rs0; l1 = l1 * c1 + rs1;
#pragma unroll
            for (int ni = 0; ni < 16; ni++) {
                acc[ni].x *= c0; acc[ni].y *= c0;
                acc[ni].z *= c1; acc[ni].w *= c1;
            }

#pragma unroll
            for (int kf = 0; kf < 4; kf++) {
                const uint32_t* vr0 = Vr + (kt2 * 32 + kf * 8 + lc) * 136;
                const uint32_t* vr1 = Vr + (kt2 * 32 + kf * 8 + lc + 4) * 136;
#pragma unroll
                for (int ni = 0; ni < 16; ni++)
                    mma_bf16(acc[ni], pa[kf], vr0[ni * 8 + lr], vr1[ni * 8 + lr]);
            }
        }

        if (vh == 0) {
            __syncthreads();        // raw scores visible; attention done with V0
            if (warp < 2) {         // exact softmax over full 256 keys
                const int m = warp;
                float sc[8];
                float tmax = -INFINITY;
#pragma unroll
                for (int j = 0; j < 8; j++) {
                    sc[j] = ps[m * 256 + j * 32 + lane];
                    tmax = fmaxf(tmax, sc[j]);
                }
                tmax = warp_max32(tmax);
                float lsum = 0.f;
#pragma unroll
                for (int j = 0; j < 8; j++) {
                    const float p = __expf(sc[j] - tmax);
                    ps[m * 256 + j * 32 + lane] = p;
                    lsum += p;
                }
                lsum = warp_sum32(lsum);
                if (lane == 0) lsm[m] = lsum;
            }
            __syncthreads();        // ps normalized visible

            // rep-V accumulation for half 0
            if (tid < 128) {
                const int ml = tid >> 6, dp = tid & 63;
                float rv0 = 0.f, rv1 = 0.f;
                const float* pm = ps + ml * 256;
#pragma unroll 4
                for (int kp = 0; kp < 64; kp++) {
                    const float p0 = pm[2 * kp], p1 = pm[2 * kp + 1];
                    const uint2 vv = *(const uint2*)&Vr[kp * 136 + 2 * dp];
                    rv0 += p0 * bflo(vv.x) + p1 * bfhi(vv.x);
                    rv1 += p0 * bflo(vv.y) + p1 * bfhi(vv.y);
                }
                rva[ml * 128 + 2 * dp]     = rv0;
                rva[ml * 128 + 2 * dp + 1] = rv1;
            }
        }
    }

    // ---- attention write-out ----
    {
        const float inv0 = 1.f / l0, inv1 = 1.f / l1;
        uint32_t* o0 = g_outLb + (size_t)n0g * 256 + h * 64;
        uint32_t* o1 = g_outLb + (size_t)n1g * 256 + h * 64;
#pragma unroll
        for (int ni = 0; ni < 16; ni++) {
            o0[ni * 4 + lc] = bf2(acc[ni].x * inv0, acc[ni].y * inv0);
            o1[ni * 4 + lc] = bf2(acc[ni].z * inv1, acc[ni].w * inv1);
        }
    }

    // ---- rep-V half 1 + rep-K (resident K) + write reps ----
    if (tid < 128) {
        const int ml = tid >> 6, dp = tid & 63;
        const float inv = 1.f / lsm[ml];
        const float* pm = ps + ml * 256;

        float rv0 = rva[ml * 128 + 2 * dp];
        float rv1 = rva[ml * 128 + 2 * dp + 1];
#pragma unroll 4
        for (int kp = 0; kp < 64; kp++) {          // half-1 V (resident now)
            const float p0 = pm[128 + 2 * kp], p1 = pm[128 + 2 * kp + 1];
            const uint2 vv = *(const uint2*)&Vr[kp * 136 + 2 * dp];
            rv0 += p0 * bflo(vv.x) + p1 * bfhi(vv.x);
            rv1 += p0 * bflo(vv.y) + p1 * bfhi(vv.y);
        }

        float rk0 = 0.f, rk1 = 0.f;
#pragma unroll 4
        for (int kp = 0; kp < 128; kp++) {         // full resident K
            const float p0 = pm[2 * kp], p1 = pm[2 * kp + 1];
            const uint32_t ka = Kr[(2 * kp) * 68 + dp];
            const uint32_t kb = Kr[(2 * kp + 1) * 68 + dp];
            rk0 += p0 * bflo(ka) + p1 * bflo(kb);
            rk1 += p0 * bfhi(ka) + p1 * bfhi(kb);
        }

        const int r = kpart * MM + zs * 2 + ml;
        g_repKb[(size_t)r * 256 + h * 64 + dp] = bf2(rk0 * inv, rk1 * inv);
        rva[ml * 128 + 2 * dp]     = rv0 * inv;
        rva[ml * 128 + 2 * dp + 1] = rv1 * inv;
    }
    __syncthreads();
    if (tid < 128) {
        const int rpair = kpart * 2 + zs;
        g_repVb2[(size_t)rpair * 512 + h * 128 + tid] =
            bf2(rva[tid], rva[128 + tid]);
    }
}

// ---------------------------------------------------------------------------
// Kernel 3: global cross-attention; cp.async double-buffered K/V tiles.
// ---------------------------------------------------------------------------
#define GA_BUF 8704
#define GA_SMEM_BYTES (2 * GA_BUF * 4)

__global__ __launch_bounds__(256) void global_attn()
{
    extern __shared__ uint32_t sg[];

    const int tid = threadIdx.x, warp = tid >> 5, lane = tid & 31;
    const int lr = lane >> 2, lc = lane & 3;
    const int h = blockIdx.y;
    const int q0 = blockIdx.x * 128;
    const int wq = warp * 16;
    const int n0g = q0 + wq + lr, n1g = q0 + wq + lr + 8;
    const uint32_t sbase = smem_u32addr(sg);

    auto issueG = [&](int t, int b) {
        const uint32_t base = sbase + b * GA_BUF * 4;
#pragma unroll
        for (int j = 0; j < 8; j++) {
            const int cid = tid * 8 + j;
            if (cid < 1024) {
                const int row = cid >> 4, c4 = (cid & 15) * 4;
                CP_ASYNC16(base + (row * 68 + c4) * 4,
                           g_repKb + (size_t)(t + row) * 256 + h * 64 + c4);
            } else {
                const int cid2 = cid - 1024;
                const int kpi = cid2 >> 5, c4 = (cid2 & 31) * 4;
                CP_ASYNC16(base + (64 * 68 + kpi * 136 + c4) * 4,
                           g_repVb2 + (size_t)((t >> 1) + kpi) * 512 + h * 128 + c4);
            }
        }
    };

    uint32_t qa[8][4];
    {
        const uint32_t* q0p = g_Qb + (size_t)n0g * 256 + h * 64;
        const uint32_t* q1p = g_Qb + (size_t)n1g * 256 + h * 64;
#pragma unroll
        for (int kf = 0; kf < 8; kf++) {
            qa[kf][0] = q0p[kf * 8 + lc];
            qa[kf][1] = q1p[kf * 8 + lc];
            qa[kf][2] = q0p[kf * 8 + lc + 4];
            qa[kf][3] = q1p[kf * 8 + lc + 4];
        }
    }

    float4 acc[16];
#pragma unroll
    for (int ni = 0; ni < 16; ni++) acc[ni] = make_float4(0.f, 0.f, 0.f, 0.f);
    float m0 = -INFINITY, m1 = -INFINITY, l0 = 0.f, l1 = 0.f;

    issueG(0, 0);  CP_COMMIT();
    issueG(64, 1); CP_COMMIT();

    for (int ti = 0; ti < 8; ti++) {
        if (ti < 7) CP_WAIT(1); else CP_WAIT(0);
        __syncthreads();

        const uint32_t* Kr = sg + (ti & 1) * GA_BUF;
        const uint32_t* Vr = Kr + 64 * 68;

        float4 s[8];
#pragma unroll
        for (int ni = 0; ni < 8; ni++) s[ni] = make_float4(0.f, 0.f, 0.f, 0.f);
#pragma unroll
        for (int kf = 0; kf < 8; kf++) {
#pragma unroll
            for (int ni = 0; ni < 8; ni++) {
                const uint32_t* kr = Kr + (ni * 8 + lr) * 68 + kf * 8;
                mma_bf16(s[ni], qa[kf], kr[lc], kr[lc + 4]);
            }
        }

        float tm0 = -INFINITY, tm1 = -INFINITY;
#pragma unroll
        for (int ni = 0; ni < 8; ni++) {
            tm0 = fmaxf(tm0, fmaxf(s[ni].x, s[ni].y));
            tm1 = fmaxf(tm1, fmaxf(s[ni].z, s[ni].w));
        }
        tm0 = warp_max2(tm0); tm1 = warp_max2(tm1);
        const float mn0 = fmaxf(m0, tm0), mn1 = fmaxf(m1, tm1);
        const float c0 = __expf(m0 - mn0), c1 = __expf(m1 - mn1);
        m0 = mn0; m1 = mn1;

        float rs0 = 0.f, rs1 = 0.f;
        uint32_t pa[4][4];
#pragma unroll
        for (int ni = 0; ni < 8; ni++) {
            const float p0 = __expf(s[ni].x - mn0);
            const float p1 = __expf(s[ni].y - mn0);
            const float p2 = __expf(s[ni].z - mn1);
            const float p3 = __expf(s[ni].w - mn1);
            rs0 += p0 + p1; rs1 += p2 + p3;
            pa[ni >> 1][(ni & 1) * 2 + 0] = bf2(p0, p1);
            pa[ni >> 1][(ni & 1) * 2 + 1] = bf2(p2, p3);
        }
        rs0 = warp_sum2(rs0); rs1 = warp_sum2(rs1);
        l0 = l0 * c0 + rs0; l1 = l1 * c1 + rs1;
#pragma unroll
        for (int ni = 0; ni < 16; ni++) {
            acc[ni].x *= c0; acc[ni].y *= c0;
            acc[ni].z *= c1; acc[ni].w *= c1;
        }

#pragma unroll
        for (int kf = 0; kf < 4; kf++) {
            const uint32_t* vr0 = Vr + (kf * 8 + lc) * 136;
            const uint32_t* vr1 = Vr + (kf * 8 + lc + 4) * 136;
#pragma unroll
            for (int ni = 0; ni < 16; ni++)
                mma_bf16(acc[ni], pa[kf], vr0[ni * 8 + lr], vr1[ni * 8 + lr]);
        }

        __syncthreads();
        if (ti + 2 < 8) { issueG((ti + 2) * 64, ti & 1); CP_COMMIT(); }
    }

    const float inv0 = 1.f / l0, inv1 = 1.f / l1;
    uint32_t* o0 = g_outGb + (size_t)n0g * 256 + h * 64;
    uint32_t* o1 = g_outGb + (size_t)n1g * 256 + h * 64;
#pragma unroll
    for (int ni = 0; ni < 16; ni++) {
        o0[ni * 4 + lc] = bf2(acc[ni].x * inv0, acc[ni].y * inv0);
        o1[ni * 4 + lc] = bf2(acc[ni].z * inv1, acc[ni].w * inv1);
    }
}

// ---------------------------------------------------------------------------
// Kernel 4: combine — unpack bf16 outL/outG, add exact x_self
// ---------------------------------------------------------------------------
__global__ __launch_bounds__(256) void combine(const float* __restrict__ alpha_logit,
                                               const float* __restrict__ beta_p,
                                               float* __restrict__ out)
{
    const int idx = blockIdx.x * 256 + threadIdx.x;
    const int n = idx >> 4, g = idx & 15;

    const float alpha = 1.f / (1.f + __expf(-alpha_logit[0]));
    const float beta  = beta_p[0];
    const float ca = alpha * 0.25f;
    const float cg = (1.f - alpha) * 0.25f;

    float s[8];
#pragma unroll
    for (int j = 0; j < 8; j++) s[j] = 0.f;

#pragma unroll
    for (int h = 0; h < HH; h++) {
        const size_t base = (size_t)n * 256 + h * 64 + g * 4;
        const uint4 a = *(const uint4*)&g_outLb[base];
        const uint4 b = *(const uint4*)&g_outGb[base];
        s[0] += ca * bflo(a.x) + cg * bflo(b.x);
        s[1] += ca * bfhi(a.x) + cg * bfhi(b.x);
        s[2] += ca * bflo(a.y) + cg * bflo(b.y);
        s[3] += ca * bfhi(a.y) + cg * bfhi(b.y);
        s[4] += ca * bflo(a.z) + cg * bflo(b.z);
        s[5] += ca * bfhi(a.z) + cg * bfhi(b.z);
        s[6] += ca * bflo(a.w) + cg * bflo(b.w);
        s[7] += ca * bfhi(a.w) + cg * bfhi(b.w);
    }

    const size_t ob = (size_t)n * DD + g * 8;
    const float4 xs0 = *(const float4*)&g_xself[ob];
    const float4 xs1 = *(const float4*)&g_xself[ob + 4];
    float4 o0, o1;
    o0.x = s[0] + beta * xs0.x; o0.y = s[1] + beta * xs0.y;
    o0.z = s[2] + beta * xs0.z; o0.w = s[3] + beta * xs0.w;
    o1.x = s[4] + beta * xs1.x; o1.y = s[5] + beta * xs1.y;
    o1.z = s[6] + beta * xs1.z; o1.w = s[7] + beta * xs1.w;
    *(float4*)&out[ob]     = o0;
    *(float4*)&out[ob + 4] = o1;
}

// ---------------------------------------------------------------------------
// Launcher
// ---------------------------------------------------------------------------
extern "C" void kernel_launch(void* const* d_in, const int* in_sizes, int n_in,
                              void* d_out, int out_size)
{
    (void)in_sizes; (void)n_in; (void)out_size;
    const float* x     = (const float*)d_in[0];
    const int*   pidx  = (const int*)  d_in[1];
    const float* Wq    = (const float*)d_in[2];
    const float* bq    = (const float*)d_in[3];
    const float* Wk    = (const float*)d_in[4];
    const float* bk    = (const float*)d_in[5];
    const float* Wv    = (const float*)d_in[6];
    const float* bv    = (const float*)d_in[7];
    const float* seeds = (const float*)d_in[8];
    const float* alog  = (const float*)d_in[9];
    const float* beta  = (const float*)d_in[10];
    float* out = (float*)d_out;

    const int gxsb = 2 * 4 * GSTG * 4;

    // idempotent host-state calls; capture-legal
    cudaFuncSetAttribute((const void*)qkv_gemm_tc,
                         cudaFuncAttributeMaxDynamicSharedMemorySize, GEMM_SMEM_BYTES);
    cudaFuncSetAttribute((const void*)xself_gemm,
                         cudaFuncAttributeMaxDynamicSharedMemorySize, gxsb);
    cudaFuncSetAttribute((const void*)fine_attn_pool,
                         cudaFuncAttributeMaxDynamicSharedMemorySize, FINE_SMEM_BYTES);
    cudaFuncSetAttribute((const void*)global_attn,
                         cudaFuncAttributeMaxDynamicSharedMemorySize, GA_SMEM_BYTES);

    split_xt<<<NN / 128, 256>>>(x);
    dim3 gw(128 * HD / 256, 3);
    split_w<<<gw, 256>>>(Wq, Wk, Wv);
    wavg_split<<<64, 256>>>(Wv);

    dim3 g1(HD / 128, NN / 128);               // unified A-resident QKV (R12)
    qkv_gemm_tc<<<g1, 256, GEMM_SMEM_BYTES>>>(bq, bk, bv);

    xself_gemm<<<NN / 128, 256, gxsb>>>(bv);   // exact x_self

    dim3 g2(KPP, HH, 2);                       // fine + pooling (2 blocks/SM)
    fine_attn_pool<<<g2, 256, FINE_SMEM_BYTES>>>(pidx, seeds);

    dim3 g4(NN / 128, HH);                     // global
    global_attn<<<g4, 256, GA_SMEM_BYTES>>>();

    combine<<<(NN * 16) / 256, 256>>>(alog, beta, out);
}